// round 13
// baseline (speedup 1.0000x reference)
#include <cuda_runtime.h>
#include <cuda_bf16.h>

// Contour_to_mask: winding-number mask, 512x512 px, 128 contour points.
// theta = acos(clip(cos,-1+eps,1-eps)) == clip(atan2(|cross|,dot),...); with
// theta = pi/2 -+ v (v>=0) the clamp is exactly v = min(v, pi/2-acos(1-eps)).
// cross_j = tK_j + py*exK_j, dot_j = UK_j + K*py*(py-sy_j), px folded per block.
// 2 px/thread packed f32x2, two 32-edge streams per trip (4 chains).
// 256-thread blocks split by edge half (eh = t>>7); partials combined in smem.
// NEW: batched reciprocal — ONE rcp serves all 4 ratios of a trip
// (inv of the product, recovered by multiplication), MUFU/trip 8 -> 5.

#define MSIZE 512
#define NPTS  128
#define EHALF 64
#define QE    32
#define KCONST 100000.0f
#define INV2PI 0.15915494309189535f
#define PI_2F  1.57079632679489662f
#define VMAX   1.5663241903f            /* pi/2 - acos(1 - 1e-5) */

typedef unsigned long long u64;

__device__ __forceinline__ u64 pk2(float lo, float hi) {
    u64 r; asm("mov.b64 %0,{%1,%2};" : "=l"(r) : "f"(lo), "f"(hi)); return r;
}
__device__ __forceinline__ void upk2(u64 v, float& lo, float& hi) {
    asm("mov.b64 {%0,%1},%2;" : "=f"(lo), "=f"(hi) : "l"(v));
}
__device__ __forceinline__ u64 mul2(u64 a, u64 b) {
    u64 r; asm("mul.rn.f32x2 %0,%1,%2;" : "=l"(r) : "l"(a), "l"(b)); return r;
}
__device__ __forceinline__ u64 add2(u64 a, u64 b) {
    u64 r; asm("add.rn.f32x2 %0,%1,%2;" : "=l"(r) : "l"(a), "l"(b)); return r;
}
__device__ __forceinline__ u64 fma2(u64 a, u64 b, u64 c) {
    u64 r; asm("fma.rn.f32x2 %0,%1,%2,%3;" : "=l"(r) : "l"(a), "l"(b), "l"(c)); return r;
}
__device__ __forceinline__ float ftanh(float x) {
    float r; asm("tanh.approx.f32 %0,%1;" : "=f"(r) : "f"(x)); return r;
}
__device__ __forceinline__ float frcp(float x) {
    float r; asm("rcp.approx.f32 %0,%1;" : "=f"(r) : "f"(x)); return r;
}
// +-1.0f carrying the sign of x: one LOP3
__device__ __forceinline__ float sgn1(float x) {
    return __int_as_float(0x3f800000 | (__float_as_int(x) & 0x80000000));
}

// packed (2-pixel) front-end: cross/dot + abs/minmax; no division yet
__device__ __forceinline__ void front_end(
    const ulonglong2 q0, const ulonglong2 q1,
    const u64 pyv, const u64 Kpyv,
    float& cr0, float& cr1, float& c0, float& c1,
    float& a0, float& a1, float& b0, float& b1,
    float& M0, float& M1, float& m0, float& m1)
{
    const u64 crv = fma2(pyv, q0.y, q0.x);            // K*cross
    const u64 pys = add2(pyv, q1.y);                  // py - sy
    const u64 dtv = fma2(Kpyv, pys, q1.x);            // K*dot
    upk2(crv, cr0, cr1);
    upk2(dtv, c0, c1);
    a0 = fabsf(cr0); a1 = fabsf(cr1);
    b0 = fabsf(c0);  b1 = fabsf(c1);
    M0 = fmaxf(a0, b0); M1 = fmaxf(a1, b1);
    m0 = fminf(a0, b0); m1 = fminf(a1, b1);
}

// backend for one pixel: quadrant fixup + exact clamp + tanh accumulate
__device__ __forceinline__ void backend(
    float al, float a, float b, float c, float cr, float& sum)
{
    const float h = PI_2F - al;
    float v = (b > a) ? h : al;
    v = fminf(v, VMAX);                                // exact reference clamp
    const float th = fmaf(sgn1(c), -v, PI_2F);
    sum = fmaf(ftanh(cr), th, sum);                    // cr IS K*cross
}

__global__ void __launch_bounds__(256)
contour_mask_kernel(const float* __restrict__ contour, float* __restrict__ out) {
    // flat per-edge constant table, lane-pair duplicated, 16B entries:
    // s[2e]   = (tK, tK, exK, exK)   tK = K*(w - px*ey), exK = K*ex
    // s[2e+1] = (UK, UK, -sy, -sy)   UK = K*(d + px*(px-sx))
    __shared__ float4 s[2 * NPTS];
    __shared__ float2 red[NPTS];            // partial sums from the eh=1 half
    const int t  = threadIdx.x;
    const int p  = t & 127;                 // pixel slot within block
    const int eh = t >> 7;                  // edge half: 0 -> edges 0..63, 1 -> 64..127
    const int row = blockIdx.x >> 1;
    const float px = (float)row * (1.0f / (float)MSIZE);

    // thread t fills table entry for edge e = t>>1, part = t&1
    {
        const int e = t >> 1;
        const float2 c0 = reinterpret_cast<const float2*>(contour)[e];
        const float2 c1 = reinterpret_cast<const float2*>(contour)[(e + 1) & (NPTS - 1)];
        if ((t & 1) == 0) {
            const float w  = fmaf(c0.y, c1.x, -(c0.x * c1.y));
            const float ey = c0.y - c1.y;
            const float tK  = KCONST * fmaf(-px, ey, w);
            const float exK = KCONST * (c0.x - c1.x);
            s[2 * e] = make_float4(tK, tK, exK, exK);
        } else {
            const float d  = fmaf(c0.x, c1.x, c0.y * c1.y);
            const float sx = c0.x + c1.x;
            const float UK = KCONST * fmaf(px, px - sx, d);
            const float nsy = -(c0.y + c1.y);
            s[2 * e + 1] = make_float4(UK, UK, nsy, nsy);
        }
    }
    __syncthreads();

    const int col0 = ((blockIdx.x & 1) << 8) + p;
    const float py0 = (float)col0         * (1.0f / (float)MSIZE);
    const float py1 = (float)(col0 + 128) * (1.0f / (float)MSIZE);
    const u64 pyv  = pk2(py0, py1);
    const u64 Kpyv = pk2(KCONST * py0, KCONST * py1);

    // atan poly, A&S 4.4.47-class (|err| <= 1e-5 rad on [0,1])
    const u64 A9 = pk2( 0.0208351f,  0.0208351f);
    const u64 A7 = pk2(-0.0851330f, -0.0851330f);
    const u64 A5 = pk2( 0.1801410f,  0.1801410f);
    const u64 A3 = pk2(-0.3302995f, -0.3302995f);
    const u64 A1 = pk2( 0.9998660f,  0.9998660f);

    // this half's 64-edge table
    const ulonglong2* sv = reinterpret_cast<const ulonglong2*>(s + eh * 2 * EHALF);

    // two 32-edge streams -> 4 independent chains
    float sa0 = 0.0f, sa1 = 0.0f, sb0 = 0.0f, sb1 = 0.0f;

#pragma unroll 4
    for (int j = 0; j < QE; ++j) {
        const ulonglong2 qa0 = sv[2 * j];
        const ulonglong2 qa1 = sv[2 * j + 1];
        const ulonglong2 qb0 = sv[2 * (j + QE)];
        const ulonglong2 qb1 = sv[2 * (j + QE) + 1];

        float crA0, crA1, cA0, cA1, aA0, aA1, bA0, bA1, MA0, MA1, mA0, mA1;
        float crB0, crB1, cB0, cB1, aB0, aB1, bB0, bB1, MB0, MB1, mB0, mB1;
        front_end(qa0, qa1, pyv, Kpyv, crA0, crA1, cA0, cA1,
                  aA0, aA1, bA0, bA1, MA0, MA1, mA0, mA1);
        front_end(qb0, qb1, pyv, Kpyv, crB0, crB1, cB0, cB1,
                  aB0, aB1, bB0, bB1, MB0, MB1, mB0, mB1);

        // batched reciprocal: one MUFU.RCP serves all four m/M ratios
        float PA, PB;
        upk2(mul2(pk2(MA0, MB0), pk2(MA1, MB1)), PA, PB);  // PA=MA0*MA1, PB=MB0*MB1
        const float inv  = frcp(PA * PB);
        const float invA = inv * PB;                        // 1/(MA0*MA1)
        const float invB = inv * PA;                        // 1/(MB0*MB1)
        const u64 rA = mul2(mul2(pk2(MA1, MA0), pk2(invA, invA)), pk2(mA0, mA1));
        const u64 rB = mul2(mul2(pk2(MB1, MB0), pk2(invB, invB)), pk2(mB0, mB1));

        // packed odd poly: al = atan(r), r in [0,1]
        const u64 r2A = mul2(rA, rA);
        const u64 r2B = mul2(rB, rB);
        u64 pA = fma2(A9, r2A, A7);
        u64 pB = fma2(A9, r2B, A7);
        pA = fma2(pA, r2A, A5);  pB = fma2(pB, r2B, A5);
        pA = fma2(pA, r2A, A3);  pB = fma2(pB, r2B, A3);
        pA = fma2(pA, r2A, A1);  pB = fma2(pB, r2B, A1);
        const u64 avA = mul2(pA, rA);
        const u64 avB = mul2(pB, rB);
        float alA0, alA1, alB0, alB1;
        upk2(avA, alA0, alA1);
        upk2(avB, alB0, alB1);

        backend(alA0, aA0, bA0, cA0, crA0, sa0);
        backend(alA1, aA1, bA1, cA1, crA1, sa1);
        backend(alB0, aB0, bB0, cB0, crB0, sb0);
        backend(alB1, aB1, bB1, cB1, crB1, sb1);
    }

    const float sum0 = sa0 + sb0;
    const float sum1 = sa1 + sb1;

    // in-block reduction of the two edge halves
    if (eh == 1) {
        red[p] = make_float2(sum0, sum1);
    }
    __syncthreads();
    if (eh == 0) {
        const float2 o = red[p];
        const int base = row * MSIZE + col0;
        out[base]       = fminf(fmaxf((sum0 + o.x) * INV2PI, 0.0f), 1.0f);
        out[base + 128] = fminf(fmaxf((sum1 + o.y) * INV2PI, 0.0f), 1.0f);
    }
}

extern "C" void kernel_launch(void* const* d_in, const int* in_sizes, int n_in,
                              void* d_out, int out_size) {
    const float* contour = (const float*)d_in[0];
    float* out = (float*)d_out;
    contour_mask_kernel<<<MSIZE * 2, 256>>>(contour, out);
}

// round 14
// speedup vs baseline: 1.5203x; 1.5203x over previous
#include <cuda_runtime.h>
#include <cuda_bf16.h>

// Contour_to_mask: winding-number mask, 512x512 px, 128 contour points.
// theta = acos(clip(cos,-1+eps,1-eps)) == clip(atan2(|cross|,dot),...); with
// theta = pi/2 -+ v (v>=0) the clamp is exactly v = min(v, pi/2-acos(1-eps)).
// cross_j = tK_j + py*exK_j, dot_j = UK_j + K*py*(py-sy_j), px folded per block.
// 2 px/thread packed f32x2, two 32-edge streams per trip (4 chains).
// 256-thread blocks split by edge half (eh = t>>7); partials combined in smem.
// R14: reciprocal batched PER EDGE PAIR (2 rcp -> 1, chains stay independent):
// inv = rcp(M0*M1); r0 = m0*M1*inv; r1 = m1*M0*inv.  MUFU/trip 8 -> 6.

#define MSIZE 512
#define NPTS  128
#define EHALF 64
#define QE    32
#define KCONST 100000.0f
#define INV2PI 0.15915494309189535f
#define PI_2F  1.57079632679489662f
#define VMAX   1.5663241903f            /* pi/2 - acos(1 - 1e-5) */

typedef unsigned long long u64;

__device__ __forceinline__ u64 pk2(float lo, float hi) {
    u64 r; asm("mov.b64 %0,{%1,%2};" : "=l"(r) : "f"(lo), "f"(hi)); return r;
}
__device__ __forceinline__ void upk2(u64 v, float& lo, float& hi) {
    asm("mov.b64 {%0,%1},%2;" : "=f"(lo), "=f"(hi) : "l"(v));
}
__device__ __forceinline__ u64 mul2(u64 a, u64 b) {
    u64 r; asm("mul.rn.f32x2 %0,%1,%2;" : "=l"(r) : "l"(a), "l"(b)); return r;
}
__device__ __forceinline__ u64 add2(u64 a, u64 b) {
    u64 r; asm("add.rn.f32x2 %0,%1,%2;" : "=l"(r) : "l"(a), "l"(b)); return r;
}
__device__ __forceinline__ u64 fma2(u64 a, u64 b, u64 c) {
    u64 r; asm("fma.rn.f32x2 %0,%1,%2,%3;" : "=l"(r) : "l"(a), "l"(b), "l"(c)); return r;
}
__device__ __forceinline__ float ftanh(float x) {
    float r; asm("tanh.approx.f32 %0,%1;" : "=f"(r) : "f"(x)); return r;
}
__device__ __forceinline__ float frcp(float x) {
    float r; asm("rcp.approx.f32 %0,%1;" : "=f"(r) : "f"(x)); return r;
}
// +-1.0f carrying the sign of x: one LOP3
__device__ __forceinline__ float sgn1(float x) {
    return __int_as_float(0x3f800000 | (__float_as_int(x) & 0x80000000));
}

// one packed (2-pixel) edge evaluation; accumulates into sum0/sum1.
// Identical to the proven R12 body except the two rcps are batched into one.
__device__ __forceinline__ void edge_eval(
    const ulonglong2 q0, const ulonglong2 q1,
    const u64 pyv, const u64 Kpyv,
    const u64 A9, const u64 A7, const u64 A5, const u64 A3, const u64 A1,
    float& sum0, float& sum1)
{
    const u64 crv = fma2(pyv, q0.y, q0.x);            // K*cross
    const u64 pys = add2(pyv, q1.y);                  // py - sy
    const u64 dtv = fma2(Kpyv, pys, q1.x);            // K*dot

    float cr0, cr1, c0, c1;
    upk2(crv, cr0, cr1);
    upk2(dtv, c0, c1);

    const float a0 = fabsf(cr0), a1 = fabsf(cr1);
    const float b0 = fabsf(c0),  b1 = fabsf(c1);
    const float M0 = fmaxf(a0, b0), M1 = fmaxf(a1, b1);
    const float m0 = fminf(a0, b0), m1 = fminf(a1, b1);

    // batched reciprocal within this chain: one MUFU.RCP for both pixels
    const float inv = frcp(M0 * M1);
    const u64 rv = mul2(mul2(pk2(m0, m1), pk2(M1, M0)), pk2(inv, inv));

    const u64 r2v = mul2(rv, rv);
    u64 pv = fma2(A9, r2v, A7);
    pv = fma2(pv, r2v, A5);
    pv = fma2(pv, r2v, A3);
    pv = fma2(pv, r2v, A1);
    const u64 av = mul2(pv, rv);
    float al0, al1;
    upk2(av, al0, al1);

    // v = angle from dot axis in [0, pi/2]; th = pi/2 - sign(dot)*v
    const float h0 = PI_2F - al0;
    const float h1 = PI_2F - al1;
    float v0 = (b0 > a0) ? h0 : al0;
    float v1 = (b1 > a1) ? h1 : al1;
    v0 = fminf(v0, VMAX);                              // exact reference clamp
    v1 = fminf(v1, VMAX);
    const float th0 = fmaf(sgn1(c0), -v0, PI_2F);
    const float th1 = fmaf(sgn1(c1), -v1, PI_2F);

    sum0 = fmaf(ftanh(cr0), th0, sum0);                // cr IS K*cross
    sum1 = fmaf(ftanh(cr1), th1, sum1);
}

__global__ void __launch_bounds__(256)
contour_mask_kernel(const float* __restrict__ contour, float* __restrict__ out) {
    // flat per-edge constant table, lane-pair duplicated, 16B entries:
    // s[2e]   = (tK, tK, exK, exK)   tK = K*(w - px*ey), exK = K*ex
    // s[2e+1] = (UK, UK, -sy, -sy)   UK = K*(d + px*(px-sx))
    __shared__ float4 s[2 * NPTS];
    __shared__ float2 red[NPTS];            // partial sums from the eh=1 half
    const int t  = threadIdx.x;
    const int p  = t & 127;                 // pixel slot within block
    const int eh = t >> 7;                  // edge half: 0 -> edges 0..63, 1 -> 64..127
    const int row = blockIdx.x >> 1;
    const float px = (float)row * (1.0f / (float)MSIZE);

    // thread t fills table entry for edge e = t>>1, part = t&1
    {
        const int e = t >> 1;
        const float2 c0 = reinterpret_cast<const float2*>(contour)[e];
        const float2 c1 = reinterpret_cast<const float2*>(contour)[(e + 1) & (NPTS - 1)];
        if ((t & 1) == 0) {
            const float w  = fmaf(c0.y, c1.x, -(c0.x * c1.y));
            const float ey = c0.y - c1.y;
            const float tK  = KCONST * fmaf(-px, ey, w);
            const float exK = KCONST * (c0.x - c1.x);
            s[2 * e] = make_float4(tK, tK, exK, exK);
        } else {
            const float d  = fmaf(c0.x, c1.x, c0.y * c1.y);
            const float sx = c0.x + c1.x;
            const float UK = KCONST * fmaf(px, px - sx, d);
            const float nsy = -(c0.y + c1.y);
            s[2 * e + 1] = make_float4(UK, UK, nsy, nsy);
        }
    }
    __syncthreads();

    const int col0 = ((blockIdx.x & 1) << 8) + p;
    const float py0 = (float)col0         * (1.0f / (float)MSIZE);
    const float py1 = (float)(col0 + 128) * (1.0f / (float)MSIZE);
    const u64 pyv  = pk2(py0, py1);
    const u64 Kpyv = pk2(KCONST * py0, KCONST * py1);

    // atan poly, A&S 4.4.47-class (|err| <= 1e-5 rad on [0,1])
    const u64 A9 = pk2( 0.0208351f,  0.0208351f);
    const u64 A7 = pk2(-0.0851330f, -0.0851330f);
    const u64 A5 = pk2( 0.1801410f,  0.1801410f);
    const u64 A3 = pk2(-0.3302995f, -0.3302995f);
    const u64 A1 = pk2( 0.9998660f,  0.9998660f);

    // this half's 64-edge table
    const ulonglong2* sv = reinterpret_cast<const ulonglong2*>(s + eh * 2 * EHALF);

    // two 32-edge streams -> 4 independent chains
    float sa0 = 0.0f, sa1 = 0.0f, sb0 = 0.0f, sb1 = 0.0f;

#pragma unroll 4
    for (int j = 0; j < QE; ++j) {
        const ulonglong2 qa0 = sv[2 * j];
        const ulonglong2 qa1 = sv[2 * j + 1];
        const ulonglong2 qb0 = sv[2 * (j + QE)];
        const ulonglong2 qb1 = sv[2 * (j + QE) + 1];
        edge_eval(qa0, qa1, pyv, Kpyv, A9, A7, A5, A3, A1, sa0, sa1);
        edge_eval(qb0, qb1, pyv, Kpyv, A9, A7, A5, A3, A1, sb0, sb1);
    }

    const float sum0 = sa0 + sb0;
    const float sum1 = sa1 + sb1;

    // in-block reduction of the two edge halves
    if (eh == 1) {
        red[p] = make_float2(sum0, sum1);
    }
    __syncthreads();
    if (eh == 0) {
        const float2 o = red[p];
        const int base = row * MSIZE + col0;
        out[base]       = fminf(fmaxf((sum0 + o.x) * INV2PI, 0.0f), 1.0f);
        out[base + 128] = fminf(fmaxf((sum1 + o.y) * INV2PI, 0.0f), 1.0f);
    }
}

extern "C" void kernel_launch(void* const* d_in, const int* in_sizes, int n_in,
                              void* d_out, int out_size) {
    const float* contour = (const float*)d_in[0];
    float* out = (float*)d_out;
    contour_mask_kernel<<<MSIZE * 2, 256>>>(contour, out);
}

// round 15
// speedup vs baseline: 1.5219x; 1.0010x over previous
#include <cuda_runtime.h>
#include <cuda_bf16.h>

// Contour_to_mask: winding-number mask, 512x512 px, 128 contour points.
// theta = acos(clip(cos,-1+eps,1-eps)) == clip(atan2(|cross|,dot),...); with
// theta = pi/2 -+ v (v>=0) the clamp is exactly v = min(v, pi/2-acos(1-eps)).
// cross_j = tK_j + py*exK_j, dot_j = UK_j + K*py*(py-sy_j), px folded per block.
// 2 px/thread packed f32x2, two 32-edge streams per trip (4 chains).
// 256-thread blocks split by edge half (eh = t>>7); partials combined in smem.
// Per-chain batched reciprocal (2 rcp -> 1): MUFU/trip = 6.
// R15: unroll 8 + pointer-bump smem indexing (loop overhead -> ~0, wider
// scheduling window for chain interleave).

#define MSIZE 512
#define NPTS  128
#define EHALF 64
#define QE    32
#define KCONST 100000.0f
#define INV2PI 0.15915494309189535f
#define PI_2F  1.57079632679489662f
#define VMAX   1.5663241903f            /* pi/2 - acos(1 - 1e-5) */

typedef unsigned long long u64;

__device__ __forceinline__ u64 pk2(float lo, float hi) {
    u64 r; asm("mov.b64 %0,{%1,%2};" : "=l"(r) : "f"(lo), "f"(hi)); return r;
}
__device__ __forceinline__ void upk2(u64 v, float& lo, float& hi) {
    asm("mov.b64 {%0,%1},%2;" : "=f"(lo), "=f"(hi) : "l"(v));
}
__device__ __forceinline__ u64 mul2(u64 a, u64 b) {
    u64 r; asm("mul.rn.f32x2 %0,%1,%2;" : "=l"(r) : "l"(a), "l"(b)); return r;
}
__device__ __forceinline__ u64 add2(u64 a, u64 b) {
    u64 r; asm("add.rn.f32x2 %0,%1,%2;" : "=l"(r) : "l"(a), "l"(b)); return r;
}
__device__ __forceinline__ u64 fma2(u64 a, u64 b, u64 c) {
    u64 r; asm("fma.rn.f32x2 %0,%1,%2,%3;" : "=l"(r) : "l"(a), "l"(b), "l"(c)); return r;
}
__device__ __forceinline__ float ftanh(float x) {
    float r; asm("tanh.approx.f32 %0,%1;" : "=f"(r) : "f"(x)); return r;
}
__device__ __forceinline__ float frcp(float x) {
    float r; asm("rcp.approx.f32 %0,%1;" : "=f"(r) : "f"(x)); return r;
}
// +-1.0f carrying the sign of x: one LOP3
__device__ __forceinline__ float sgn1(float x) {
    return __int_as_float(0x3f800000 | (__float_as_int(x) & 0x80000000));
}

// one packed (2-pixel) edge evaluation; accumulates into sum0/sum1.
// R14-proven body: per-chain batched reciprocal (one MUFU.RCP per 2 pixels).
__device__ __forceinline__ void edge_eval(
    const ulonglong2 q0, const ulonglong2 q1,
    const u64 pyv, const u64 Kpyv,
    const u64 A9, const u64 A7, const u64 A5, const u64 A3, const u64 A1,
    float& sum0, float& sum1)
{
    const u64 crv = fma2(pyv, q0.y, q0.x);            // K*cross
    const u64 pys = add2(pyv, q1.y);                  // py - sy
    const u64 dtv = fma2(Kpyv, pys, q1.x);            // K*dot

    float cr0, cr1, c0, c1;
    upk2(crv, cr0, cr1);
    upk2(dtv, c0, c1);

    const float a0 = fabsf(cr0), a1 = fabsf(cr1);
    const float b0 = fabsf(c0),  b1 = fabsf(c1);
    const float M0 = fmaxf(a0, b0), M1 = fmaxf(a1, b1);
    const float m0 = fminf(a0, b0), m1 = fminf(a1, b1);

    // batched reciprocal within this chain: one MUFU.RCP for both pixels
    const float inv = frcp(M0 * M1);
    const u64 rv = mul2(mul2(pk2(m0, m1), pk2(M1, M0)), pk2(inv, inv));

    const u64 r2v = mul2(rv, rv);
    u64 pv = fma2(A9, r2v, A7);
    pv = fma2(pv, r2v, A5);
    pv = fma2(pv, r2v, A3);
    pv = fma2(pv, r2v, A1);
    const u64 av = mul2(pv, rv);
    float al0, al1;
    upk2(av, al0, al1);

    // v = angle from dot axis in [0, pi/2]; th = pi/2 - sign(dot)*v
    const float h0 = PI_2F - al0;
    const float h1 = PI_2F - al1;
    float v0 = (b0 > a0) ? h0 : al0;
    float v1 = (b1 > a1) ? h1 : al1;
    v0 = fminf(v0, VMAX);                              // exact reference clamp
    v1 = fminf(v1, VMAX);
    const float th0 = fmaf(sgn1(c0), -v0, PI_2F);
    const float th1 = fmaf(sgn1(c1), -v1, PI_2F);

    sum0 = fmaf(ftanh(cr0), th0, sum0);                // cr IS K*cross
    sum1 = fmaf(ftanh(cr1), th1, sum1);
}

__global__ void __launch_bounds__(256)
contour_mask_kernel(const float* __restrict__ contour, float* __restrict__ out) {
    // flat per-edge constant table, lane-pair duplicated, 16B entries:
    // s[2e]   = (tK, tK, exK, exK)   tK = K*(w - px*ey), exK = K*ex
    // s[2e+1] = (UK, UK, -sy, -sy)   UK = K*(d + px*(px-sx))
    __shared__ float4 s[2 * NPTS];
    __shared__ float2 red[NPTS];            // partial sums from the eh=1 half
    const int t  = threadIdx.x;
    const int p  = t & 127;                 // pixel slot within block
    const int eh = t >> 7;                  // edge half: 0 -> edges 0..63, 1 -> 64..127
    const int row = blockIdx.x >> 1;
    const float px = (float)row * (1.0f / (float)MSIZE);

    // thread t fills table entry for edge e = t>>1, part = t&1
    {
        const int e = t >> 1;
        const float2 c0 = reinterpret_cast<const float2*>(contour)[e];
        const float2 c1 = reinterpret_cast<const float2*>(contour)[(e + 1) & (NPTS - 1)];
        if ((t & 1) == 0) {
            const float w  = fmaf(c0.y, c1.x, -(c0.x * c1.y));
            const float ey = c0.y - c1.y;
            const float tK  = KCONST * fmaf(-px, ey, w);
            const float exK = KCONST * (c0.x - c1.x);
            s[2 * e] = make_float4(tK, tK, exK, exK);
        } else {
            const float d  = fmaf(c0.x, c1.x, c0.y * c1.y);
            const float sx = c0.x + c1.x;
            const float UK = KCONST * fmaf(px, px - sx, d);
            const float nsy = -(c0.y + c1.y);
            s[2 * e + 1] = make_float4(UK, UK, nsy, nsy);
        }
    }
    __syncthreads();

    const int col0 = ((blockIdx.x & 1) << 8) + p;
    const float py0 = (float)col0         * (1.0f / (float)MSIZE);
    const float py1 = (float)(col0 + 128) * (1.0f / (float)MSIZE);
    const u64 pyv  = pk2(py0, py1);
    const u64 Kpyv = pk2(KCONST * py0, KCONST * py1);

    // atan poly, A&S 4.4.47-class (|err| <= 1e-5 rad on [0,1])
    const u64 A9 = pk2( 0.0208351f,  0.0208351f);
    const u64 A7 = pk2(-0.0851330f, -0.0851330f);
    const u64 A5 = pk2( 0.1801410f,  0.1801410f);
    const u64 A3 = pk2(-0.3302995f, -0.3302995f);
    const u64 A1 = pk2( 0.9998660f,  0.9998660f);

    // this half's 64-edge table; two 32-edge streams via bumped pointers
    const ulonglong2* pa = reinterpret_cast<const ulonglong2*>(s + eh * 2 * EHALF);
    const ulonglong2* pb = pa + 2 * QE;

    float sa0 = 0.0f, sa1 = 0.0f, sb0 = 0.0f, sb1 = 0.0f;

#pragma unroll 8
    for (int j = 0; j < QE; ++j) {
        const ulonglong2 qa0 = pa[0];
        const ulonglong2 qa1 = pa[1];
        const ulonglong2 qb0 = pb[0];
        const ulonglong2 qb1 = pb[1];
        pa += 2; pb += 2;
        edge_eval(qa0, qa1, pyv, Kpyv, A9, A7, A5, A3, A1, sa0, sa1);
        edge_eval(qb0, qb1, pyv, Kpyv, A9, A7, A5, A3, A1, sb0, sb1);
    }

    const float sum0 = sa0 + sb0;
    const float sum1 = sa1 + sb1;

    // in-block reduction of the two edge halves
    if (eh == 1) {
        red[p] = make_float2(sum0, sum1);
    }
    __syncthreads();
    if (eh == 0) {
        const float2 o = red[p];
        const int base = row * MSIZE + col0;
        out[base]       = fminf(fmaxf((sum0 + o.x) * INV2PI, 0.0f), 1.0f);
        out[base + 128] = fminf(fmaxf((sum1 + o.y) * INV2PI, 0.0f), 1.0f);
    }
}

extern "C" void kernel_launch(void* const* d_in, const int* in_sizes, int n_in,
                              void* d_out, int out_size) {
    const float* contour = (const float*)d_in[0];
    float* out = (float*)d_out;
    contour_mask_kernel<<<MSIZE * 2, 256>>>(contour, out);
}

// round 16
// speedup vs baseline: 1.5328x; 1.0072x over previous
#include <cuda_runtime.h>
#include <cuda_bf16.h>

// Contour_to_mask: winding-number mask, 512x512 px, 128 contour points.
// theta = acos(clip(cos,-1+eps,1-eps)) == clip(atan2(|cross|,dot),...); with
// theta = pi/2 -+ v (v>=0) the clamp is exactly v = min(v, pi/2-acos(1-eps)).
// cross_j = tK_j + py*exK_j, dot_j = UK_j + K*py*(py-sy_j), px folded per block.
// 2 px/thread packed f32x2, two 32-edge streams per trip (4 chains).
// 256-thread blocks split by edge half (eh = t>>7); partials combined in smem.
// R16: ONE scalar rcp per trip serves all 4 ratios (inv of PA*PB, recovered by
// muls; PA/PB already needed). MUFU/trip 6 -> 5 (4 tanh + 1 rcp) — the kernel
// is measured to be exactly MUFU-throughput-bound, so floor drops 48->40 cyc.

#define MSIZE 512
#define NPTS  128
#define EHALF 64
#define QE    32
#define KCONST 100000.0f
#define INV2PI 0.15915494309189535f
#define PI_2F  1.57079632679489662f
#define VMAX   1.5663241903f            /* pi/2 - acos(1 - 1e-5) */

typedef unsigned long long u64;

__device__ __forceinline__ u64 pk2(float lo, float hi) {
    u64 r; asm("mov.b64 %0,{%1,%2};" : "=l"(r) : "f"(lo), "f"(hi)); return r;
}
__device__ __forceinline__ void upk2(u64 v, float& lo, float& hi) {
    asm("mov.b64 {%0,%1},%2;" : "=f"(lo), "=f"(hi) : "l"(v));
}
__device__ __forceinline__ u64 mul2(u64 a, u64 b) {
    u64 r; asm("mul.rn.f32x2 %0,%1,%2;" : "=l"(r) : "l"(a), "l"(b)); return r;
}
__device__ __forceinline__ u64 add2(u64 a, u64 b) {
    u64 r; asm("add.rn.f32x2 %0,%1,%2;" : "=l"(r) : "l"(a), "l"(b)); return r;
}
__device__ __forceinline__ u64 fma2(u64 a, u64 b, u64 c) {
    u64 r; asm("fma.rn.f32x2 %0,%1,%2,%3;" : "=l"(r) : "l"(a), "l"(b), "l"(c)); return r;
}
__device__ __forceinline__ float ftanh(float x) {
    float r; asm("tanh.approx.f32 %0,%1;" : "=f"(r) : "f"(x)); return r;
}
__device__ __forceinline__ float frcp(float x) {
    float r; asm("rcp.approx.f32 %0,%1;" : "=f"(r) : "f"(x)); return r;
}
// +-1.0f carrying the sign of x: one LOP3
__device__ __forceinline__ float sgn1(float x) {
    return __int_as_float(0x3f800000 | (__float_as_int(x) & 0x80000000));
}

__global__ void __launch_bounds__(256)
contour_mask_kernel(const float* __restrict__ contour, float* __restrict__ out) {
    // flat per-edge constant table, lane-pair duplicated, 16B entries:
    // s[2e]   = (tK, tK, exK, exK)   tK = K*(w - px*ey), exK = K*ex
    // s[2e+1] = (UK, UK, -sy, -sy)   UK = K*(d + px*(px-sx))
    __shared__ float4 s[2 * NPTS];
    __shared__ float2 red[NPTS];            // partial sums from the eh=1 half
    const int t  = threadIdx.x;
    const int p  = t & 127;                 // pixel slot within block
    const int eh = t >> 7;                  // edge half: 0 -> edges 0..63, 1 -> 64..127
    const int row = blockIdx.x >> 1;
    const float px = (float)row * (1.0f / (float)MSIZE);

    // thread t fills table entry for edge e = t>>1, part = t&1
    {
        const int e = t >> 1;
        const float2 c0 = reinterpret_cast<const float2*>(contour)[e];
        const float2 c1 = reinterpret_cast<const float2*>(contour)[(e + 1) & (NPTS - 1)];
        if ((t & 1) == 0) {
            const float w  = fmaf(c0.y, c1.x, -(c0.x * c1.y));
            const float ey = c0.y - c1.y;
            const float tK  = KCONST * fmaf(-px, ey, w);
            const float exK = KCONST * (c0.x - c1.x);
            s[2 * e] = make_float4(tK, tK, exK, exK);
        } else {
            const float d  = fmaf(c0.x, c1.x, c0.y * c1.y);
            const float sx = c0.x + c1.x;
            const float UK = KCONST * fmaf(px, px - sx, d);
            const float nsy = -(c0.y + c1.y);
            s[2 * e + 1] = make_float4(UK, UK, nsy, nsy);
        }
    }
    __syncthreads();

    const int col0 = ((blockIdx.x & 1) << 8) + p;
    const float py0 = (float)col0         * (1.0f / (float)MSIZE);
    const float py1 = (float)(col0 + 128) * (1.0f / (float)MSIZE);
    const u64 pyv  = pk2(py0, py1);
    const u64 Kpyv = pk2(KCONST * py0, KCONST * py1);

    // atan poly, A&S 4.4.47-class (|err| <= 1e-5 rad on [0,1])
    const u64 A9 = pk2( 0.0208351f,  0.0208351f);
    const u64 A7 = pk2(-0.0851330f, -0.0851330f);
    const u64 A5 = pk2( 0.1801410f,  0.1801410f);
    const u64 A3 = pk2(-0.3302995f, -0.3302995f);
    const u64 A1 = pk2( 0.9998660f,  0.9998660f);

    // this half's 64-edge table; two 32-edge streams via bumped pointers
    const ulonglong2* pa = reinterpret_cast<const ulonglong2*>(s + eh * 2 * EHALF);
    const ulonglong2* pb = pa + 2 * QE;

    float sa0 = 0.0f, sa1 = 0.0f, sb0 = 0.0f, sb1 = 0.0f;

#pragma unroll 8
    for (int j = 0; j < QE; ++j) {
        const ulonglong2 qa0 = pa[0];
        const ulonglong2 qa1 = pa[1];
        const ulonglong2 qb0 = pb[0];
        const ulonglong2 qb1 = pb[1];
        pa += 2; pb += 2;

        // ---- front-end, chain A ----
        const u64 crvA = fma2(pyv, qa0.y, qa0.x);         // K*cross
        const u64 pysA = add2(pyv, qa1.y);                // py - sy
        const u64 dtvA = fma2(Kpyv, pysA, qa1.x);         // K*dot
        float crA0, crA1, cA0, cA1;
        upk2(crvA, crA0, crA1);
        upk2(dtvA, cA0, cA1);
        const float aA0 = fabsf(crA0), aA1 = fabsf(crA1);
        const float bA0 = fabsf(cA0),  bA1 = fabsf(cA1);
        const float MA0 = fmaxf(aA0, bA0), MA1 = fmaxf(aA1, bA1);
        const float mA0 = fminf(aA0, bA0), mA1 = fminf(aA1, bA1);
        const float PA  = MA0 * MA1;

        // ---- front-end, chain B ----
        const u64 crvB = fma2(pyv, qb0.y, qb0.x);
        const u64 pysB = add2(pyv, qb1.y);
        const u64 dtvB = fma2(Kpyv, pysB, qb1.x);
        float crB0, crB1, cB0, cB1;
        upk2(crvB, crB0, crB1);
        upk2(dtvB, cB0, cB1);
        const float aB0 = fabsf(crB0), aB1 = fabsf(crB1);
        const float bB0 = fabsf(cB0),  bB1 = fabsf(cB1);
        const float MB0 = fmaxf(aB0, bB0), MB1 = fmaxf(aB1, bB1);
        const float mB0 = fminf(aB0, bB0), mB1 = fminf(aB1, bB1);
        const float PB  = MB0 * MB1;

        // ---- ONE reciprocal for all four ratios ----
        const float inv  = frcp(PA * PB);
        const float invA = inv * PB;                      // 1/(MA0*MA1)
        const float invB = inv * PA;                      // 1/(MB0*MB1)
        const u64 rA = mul2(mul2(pk2(mA0, mA1), pk2(MA1, MA0)), pk2(invA, invA));
        const u64 rB = mul2(mul2(pk2(mB0, mB1), pk2(MB1, MB0)), pk2(invB, invB));

        // ---- packed odd poly: al = atan(r), r in [0,1] ----
        const u64 r2A = mul2(rA, rA);
        const u64 r2B = mul2(rB, rB);
        u64 pvA = fma2(A9, r2A, A7);
        u64 pvB = fma2(A9, r2B, A7);
        pvA = fma2(pvA, r2A, A5);  pvB = fma2(pvB, r2B, A5);
        pvA = fma2(pvA, r2A, A3);  pvB = fma2(pvB, r2B, A3);
        pvA = fma2(pvA, r2A, A1);  pvB = fma2(pvB, r2B, A1);
        const u64 avA = mul2(pvA, rA);
        const u64 avB = mul2(pvB, rB);
        float alA0, alA1, alB0, alB1;
        upk2(avA, alA0, alA1);
        upk2(avB, alB0, alB1);

        // ---- backend: quadrant fixup + exact clamp + tanh accumulate ----
        {
            const float h = PI_2F - alA0;
            float v = (bA0 > aA0) ? h : alA0;
            v = fminf(v, VMAX);
            const float th = fmaf(sgn1(cA0), -v, PI_2F);
            sa0 = fmaf(ftanh(crA0), th, sa0);
        }
        {
            const float h = PI_2F - alA1;
            float v = (bA1 > aA1) ? h : alA1;
            v = fminf(v, VMAX);
            const float th = fmaf(sgn1(cA1), -v, PI_2F);
            sa1 = fmaf(ftanh(crA1), th, sa1);
        }
        {
            const float h = PI_2F - alB0;
            float v = (bB0 > aB0) ? h : alB0;
            v = fminf(v, VMAX);
            const float th = fmaf(sgn1(cB0), -v, PI_2F);
            sb0 = fmaf(ftanh(crB0), th, sb0);
        }
        {
            const float h = PI_2F - alB1;
            float v = (bB1 > aB1) ? h : alB1;
            v = fminf(v, VMAX);
            const float th = fmaf(sgn1(cB1), -v, PI_2F);
            sb1 = fmaf(ftanh(crB1), th, sb1);
        }
    }

    const float sum0 = sa0 + sb0;
    const float sum1 = sa1 + sb1;

    // in-block reduction of the two edge halves
    if (eh == 1) {
        red[p] = make_float2(sum0, sum1);
    }
    __syncthreads();
    if (eh == 0) {
        const float2 o = red[p];
        const int base = row * MSIZE + col0;
        out[base]       = fminf(fmaxf((sum0 + o.x) * INV2PI, 0.0f), 1.0f);
        out[base + 128] = fminf(fmaxf((sum1 + o.y) * INV2PI, 0.0f), 1.0f);
    }
}

extern "C" void kernel_launch(void* const* d_in, const int* in_sizes, int n_in,
                              void* d_out, int out_size) {
    const float* contour = (const float*)d_in[0];
    float* out = (float*)d_out;
    contour_mask_kernel<<<MSIZE * 2, 256>>>(contour, out);
}